// round 16
// baseline (speedup 1.0000x reference)
#include <cuda_runtime.h>
#include <cstdint>

// MarginalCalibrationPlot: per-(class, bin) calibration stats.
// probas: [N, C] float32 row-major, labels: [N] int32 or int64.
// Output: [confs(C*B) | accs(C*B) | n_samples(C*B)] float32, seg = c*B + b.

#define CCOUNT 100
#define NBINS  15
#define NSEG   (CCOUNT * NBINS)
#define TPB    512
#define ACTIVE 500          // active threads; multiple of CCOUNT
#define GRID_ACC 304        // 2 blocks/SM on 152-SM GB300
#define SROWS  16           // 15 real bins + 1 overflow row (p==1.0 -> w==0)
#define INV15  (1.0f / 15.0f)
#define MAGICF 12582912.0f  // 1.5 * 2^23
#define MAGICI 0x4B400000
#define FBLK   256

// Transposed per-block partials: g_pt[(chan*NSEG + k)*GRID_ACC + b].
// chan: 0=cnt, 1=sum_p, 2=sum_acc. Fully rewritten every run (no init).
// Finalize lanes read consecutive b => fully coalesced.
__device__ float g_pt[3 * NSEG * GRID_ACC];

// Converter-free binning, bit-exact vs jnp.linspace(0,1,16,f32) +
// searchsorted(side='right')-1:
//   fk = fl(fl(p*15) + 1.5*2^23)  -> mantissa low bits hold round(fl(p*15))
//   round(fl(p*15)) in {k*, k*+1}: fl(p*15) >= k* (edges map exactly to k,
//   fl monotone) and fl(p*15) <= k*+1, so one downward correction suffices.
// Validity with PRE-correction el = kf*INV15:
//   - correction fired (el > p): then p > edge[k*-...] strictly (else fl(p*15)
//     would be smaller) => valid = p > 0.01
//   - no correction (el <= p): left = el => valid = (p > el) && p > 0.01
//   combined: valid = (p > 0.01f) && (p != el).  (p==edge => w=0, exact.)
#define BINW(P, IK, W) do {                                               \
    float fk_ = fmaf((P), 15.0f, MAGICF);                                 \
    float kf_ = fk_ - MAGICF;                                             \
    float el_ = kf_ * INV15;                                              \
    IK = __float_as_int(fk_) - MAGICI;                                    \
    IK -= (el_ > (P)) ? 1 : 0;                                            \
    W = (((P) > 0.01f) && ((P) != el_)) ? 1.0f : 0.0f;                    \
} while (0)

__global__ void __launch_bounds__(TPB, 2) accum_kernel(
    const float* __restrict__ probas,
    const void*  __restrict__ labels,
    int N)
{
    // [SROWS][TPB] float2 {count, sum_p}: per-thread-private slots,
    // zero atomics / zero branches / zero converter ops in the hot loop.
    extern __shared__ float2 s2[];
    __shared__ float s_acc[NSEG];
    __shared__ int   s_ok;

    const int t = threadIdx.x;
    #pragma unroll
    for (int b = 0; b < SROWS; ++b) s2[b * TPB + t] = make_float2(0.0f, 0.0f);
    for (int i = t; i < NSEG; i += TPB) s_acc[i] = 0.0f;
    if (t == 0) s_ok = 1;
    __syncthreads();

    // labels dtype detect: int32 read as int64 pairs two labels; any
    // nonzero hi word makes v >= 2^32. P(128 hi==0 | int32) ~ 1e-256.
    {
        int nchk = (N >= 256) ? 128 : (N / 2);
        if (t < nchk) {
            long long v = ((const long long*)labels)[t];
            if (v < 0 || v >= CCOUNT) atomicAnd(&s_ok, 0);
        }
    }
    __syncthreads();
    const int sh = s_ok;                                // 1 if int64
    const int* __restrict__ l32 = (const int*)labels;   // low word = label

    const long long E     = (long long)N * CCOUNT;
    const long long units = E / ACTIVE;                 // 500-elem groups
    const int       rem   = (int)(E - units * ACTIVE);  // multiple of 100
    const long long perBlk = (units + gridDim.x - 1) / gridDim.x;
    const long long u0 = (long long)blockIdx.x * perBlk;
    long long u1 = u0 + perBlk; if (u1 > units) u1 = units;

    // ---- accuracy pass: only column labels[r] of row r can contribute.
    // 500k gathers total instead of 50M label checks in the hot loop.
    // valid => ik <= 14 (ik==15 needs p>=edge[15]=1.0 and p!=1.0: impossible).
    {
        const long long r1 = u1 * 5;
        for (long long r = u0 * 5 + t; r < r1; r += TPB) {
            int lb = l32[r << sh];
            float p = probas[r * CCOUNT + lb];
            int ik; float w; BINW(p, ik, w);
            if (w != 0.0f) atomicAdd(&s_acc[lb * NBINS + ik], 1.0f);
        }
        if (blockIdx.x == 0) {          // tail rows (N not mult of 5)
            for (long long r = units * 5 + t; r < N; r += TPB) {
                int lb = l32[r << sh];
                float p = probas[r * CCOUNT + lb];
                int ik; float w; BINW(p, ik, w);
                if (w != 0.0f) atomicAdd(&s_acc[lb * NBINS + ik], 1.0f);
            }
        }
    }

    // ---- main loop: count + sum_p only, branchless, fixed column t%100.
    #define BODY(P) do {                                                  \
        float p_ = (P);                                                   \
        int ik_; float w_; BINW(p_, ik_, w_);                             \
        float2* sp_ = &s2[ik_ * TPB + t];                                 \
        float2 v_ = *sp_;                                                 \
        v_.x += w_;                                                       \
        v_.y = fmaf(w_, p_, v_.y);                                        \
        *sp_ = v_;                                                        \
    } while (0)

    if (t < ACTIVE && u0 < u1) {
        const float* pp = probas + u0 * ACTIVE + t;
        const long long nu = u1 - u0;
        long long i = 0;
        for (; i + 8 <= nu; i += 8) {
            float p[8];
            #pragma unroll
            for (int j = 0; j < 8; ++j) p[j] = pp[j * ACTIVE];
            #pragma unroll
            for (int j = 0; j < 8; ++j) BODY(p[j]);
            pp += 8 * ACTIVE;
        }
        for (; i < nu; ++i) { BODY(pp[0]); pp += ACTIVE; }
    }
    // element tail (rem multiple of 100 => column map stays consistent)
    if (blockIdx.x == 0 && t < rem) BODY(probas[units * ACTIVE + t]);
    #undef BODY
    __syncthreads();

    // ---- epilogue: fold 5 sub-slots per (col,bin); transposed stores
    // (scattered one-shot writes here buy coalesced reads in finalize).
    const int blk = blockIdx.x;
    for (int idx = t; idx < NSEG; idx += TPB) {       // idx = col*NBINS+b
        const int b   = idx % NBINS;
        const int col = idx / NBINS;
        float cx = 0.0f, sy = 0.0f;
        #pragma unroll
        for (int j = 0; j < 5; ++j) {
            float2 v = s2[b * TPB + col + j * CCOUNT];
            cx += v.x; sy += v.y;
        }
        g_pt[(0 * NSEG + idx) * GRID_ACC + blk] = cx;
        g_pt[(1 * NSEG + idx) * GRID_ACC + blk] = sy;
        g_pt[(2 * NSEG + idx) * GRID_ACC + blk] = s_acc[idx];
    }
}

// -------- finalize: one WARP per segment, coalesced + shuffle reduce -------
__global__ void __launch_bounds__(FBLK) finalize_kernel(float* __restrict__ out) {
    const int k    = blockIdx.x * (FBLK / 32) + (threadIdx.x >> 5);
    const int lane = threadIdx.x & 31;
    if (k >= NSEG) return;

    const float* pc = g_pt + (0 * NSEG + k) * GRID_ACC;
    const float* ps = g_pt + (1 * NSEG + k) * GRID_ACC;
    const float* pa = g_pt + (2 * NSEG + k) * GRID_ACC;
    float cnt = 0.0f, sum = 0.0f, acc = 0.0f;
    for (int b = lane; b < GRID_ACC; b += 32) {
        cnt += pc[b]; sum += ps[b]; acc += pa[b];
    }
    #pragma unroll
    for (int o = 16; o > 0; o >>= 1) {
        cnt += __shfl_down_sync(0xffffffffu, cnt, o);
        sum += __shfl_down_sync(0xffffffffu, sum, o);
        acc += __shfl_down_sync(0xffffffffu, acc, o);
    }
    if (lane == 0) {
        float conf, a;
        if (cnt > 0.0f) {
            conf = sum / cnt;
            a    = acc / cnt;
        } else {
            conf = __int_as_float(0x7fc00000);
            a    = conf;
        }
        out[k]            = conf;
        out[NSEG + k]     = a;
        out[2 * NSEG + k] = cnt;
    }
}

extern "C" void kernel_launch(void* const* d_in, const int* in_sizes, int n_in,
                              void* d_out, int out_size) {
    const float* probas = (const float*)d_in[0];
    const void*  labels = d_in[1];
    const int N = in_sizes[0] / CCOUNT;

    const size_t smem = (size_t)SROWS * TPB * sizeof(float2);  // 65536 B
    cudaFuncSetAttribute(accum_kernel,
                         cudaFuncAttributeMaxDynamicSharedMemorySize, (int)smem);

    accum_kernel<<<GRID_ACC, TPB, smem>>>(probas, labels, N);
    const int warps_per_blk = FBLK / 32;
    finalize_kernel<<<(NSEG + warps_per_blk - 1) / warps_per_blk, FBLK>>>(
        (float*)d_out);
}